// round 6
// baseline (speedup 1.0000x reference)
#include <cuda_runtime.h>
#include <math.h>
#include <stdint.h>

#define BS   128
#define GS   2000
#define E    128
#define KM   4
#define NEGV (-1.0e30f)
#define CLIPV 10.0f

// ---------------- device scratch (static globals; no runtime allocation) ----------------
__device__ float d_Kc[(size_t)BS * GS * 512];   // [b][g][K1|K2|K3|K4] (524 MB)
__device__ float d_Wc[E * 512];                 // B matrix: Wc[e][j*128+f] = W_Kj[f][e]
__device__ float d_logits[BS * GS];
__device__ unsigned char d_mask[BS * GS];
__device__ int   d_vtt[BS * GS];
__device__ float d_q1[BS * E], d_q2[BS * E];
__device__ float d_iq1[BS * E], d_iq2[BS * E];
__device__ float d_Qp[BS * 512];                // [Q1|Q2|Q3|Q4] per b
__device__ float d_hmean[BS * E];
__device__ int   d_ai[BS * 4];
__device__ int   d_kl[BS * 5];
__device__ int   d_kr[BS * 4];
__device__ int   d_nol[BS];
__device__ int   d_stopped[BS];
__device__ float d_ll[BS];

// ---------------- math helpers (no MUFU in hot path) ----------------
__device__ __forceinline__ float fast_rcp(float x) {
    // x in [945, ~9000] here; bit-hack seed (~3% err) + 2 Newton steps -> ~1e-6
    float r = __uint_as_float(0x7EF311C3u - __float_as_uint(x));
    r = r * (2.0f - x * r);
    r = r * (2.0f - x * r);
    return r;
}
__device__ __forceinline__ float tanh_fast(float x) {
    // Pade(5,4) with clamp at 3.6; abs err <= ~1e-3; fma/alu pipes only
    float xc = fminf(fmaxf(x, -3.6f), 3.6f);
    float x2 = xc * xc;
    float num = xc * fmaf(x2, x2 + 105.0f, 945.0f);
    float den = fmaf(x2, fmaf(15.0f, x2, 420.0f), 945.0f);
    return num * fast_rcp(den);
}
__device__ __forceinline__ float sigmoidf_(float x) { return 1.0f / (1.0f + expf(-x)); }
__device__ __forceinline__ unsigned tf32cvt(float x) {
    unsigned r; asm("cvt.rna.tf32.f32 %0, %1;" : "=r"(r) : "f"(x)); return r;
}

// ---------------- setup kernels ----------------
__global__ void transpose_w(const float* __restrict__ W1, const float* __restrict__ W2,
                            const float* __restrict__ W3, const float* __restrict__ W4) {
    int idx = blockIdx.x * blockDim.x + threadIdx.x;    // 65536
    if (idx >= E * 512) return;
    int e = idx >> 9, n = idx & 511;
    int j = n >> 7, f = n & 127;
    const float* W = (j == 0) ? W1 : (j == 1) ? W2 : (j == 2) ? W3 : W4;
    d_Wc[idx] = W[f * E + e];
}

__global__ void hmean_kernel(const float* __restrict__ h) {
    int b = blockIdx.x, t = threadIdx.x;                 // 512 threads
    int e = t & 127, q = t >> 7;
    __shared__ float part[4][128];
    float s = 0.f;
    for (int g = q * 500; g < (q + 1) * 500; g++)
        s += h[((size_t)b * GS + g) * E + e];
    part[q][e] = s;
    __syncthreads();
    if (t < 128)
        d_hmean[b * E + t] = (part[0][t] + part[1][t] + part[2][t] + part[3][t]) * (1.0f / GS);
}

__global__ void init_kernel(const float* __restrict__ W_init, const float* __restrict__ b_init,
                            const float* __restrict__ init_query) {
    int b = blockIdx.x, t = threadIdx.x;                 // 128 threads
    __shared__ __align__(16) float sm[E];
    sm[t] = d_hmean[b * E + t];
    __syncthreads();
    float acc = b_init[t];
    const float4* w = (const float4*)(W_init + t * E);
    const float4* x = (const float4*)sm;
#pragma unroll 8
    for (int e4 = 0; e4 < E / 4; e4++) {
        float4 a = w[e4], v = x[e4];
        acc = fmaf(a.x, v.x, acc); acc = fmaf(a.y, v.y, acc);
        acc = fmaf(a.z, v.z, acc); acc = fmaf(a.w, v.w, acc);
    }
    d_q1[b * E + t] = acc;
    d_q2[b * E + t] = acc;
    float iq = init_query[t];
    d_iq1[b * E + t] = iq;
    d_iq2[b * E + t] = iq;
    if (t == 0) { d_stopped[b] = 1; d_nol[b] = -1; d_ll[b] = 0.0f; }
    if (t < 5) d_kl[b * 5 + t] = 0;
    if (t < 4) { d_ai[b * 4 + t] = 0; d_kr[b * 4 + t] = 0; }
}

// ---------------- TF32 GEMM: Kc[256000,512] = h[256000,128] @ Wc[128,512] ----------------
__global__ void __launch_bounds__(128) gemm_kernel(const float* __restrict__ A) {
    __shared__ float As[64][68];   // stride 68: 4-bank row skew -> conflict-free frags
    __shared__ float Bs[64][68];
    const int t = threadIdx.x;
    const int warp = t >> 5, lane = t & 31;
    const int m0 = blockIdx.x * 64, n0 = blockIdx.y * 64;
    const int wm = (warp >> 1) * 32, wn = (warp & 1) * 32;
    const int gi = lane >> 2, ti = lane & 3;

    float c[2][4][4];
#pragma unroll
    for (int i = 0; i < 2; i++)
#pragma unroll
        for (int j = 0; j < 4; j++)
#pragma unroll
            for (int k = 0; k < 4; k++) c[i][j][k] = 0.f;

    for (int kk = 0; kk < 128; kk += 64) {
#pragma unroll
        for (int i = t; i < 1024; i += 128) {
            int row = i >> 4, c4 = i & 15;
            *(float4*)&As[row][c4 * 4] = *(const float4*)(A + (size_t)(m0 + row) * 128 + kk + c4 * 4);
            *(float4*)&Bs[row][c4 * 4] = *(const float4*)(d_Wc + (size_t)(kk + row) * 512 + n0 + c4 * 4);
        }
        __syncthreads();
#pragma unroll
        for (int k8 = 0; k8 < 8; k8++) {
            int kb = k8 * 8;
            unsigned a[2][4], bf[4][2];
#pragma unroll
            for (int mf = 0; mf < 2; mf++) {
                int r0 = wm + mf * 16 + gi;
                a[mf][0] = tf32cvt(As[r0][kb + ti]);
                a[mf][1] = tf32cvt(As[r0 + 8][kb + ti]);
                a[mf][2] = tf32cvt(As[r0][kb + ti + 4]);
                a[mf][3] = tf32cvt(As[r0 + 8][kb + ti + 4]);
            }
#pragma unroll
            for (int nf = 0; nf < 4; nf++) {
                int cn = wn + nf * 8 + gi;
                bf[nf][0] = tf32cvt(Bs[kb + ti][cn]);
                bf[nf][1] = tf32cvt(Bs[kb + ti + 4][cn]);
            }
#pragma unroll
            for (int mf = 0; mf < 2; mf++)
#pragma unroll
                for (int nf = 0; nf < 4; nf++)
                    asm volatile(
                        "mma.sync.aligned.m16n8k8.row.col.f32.tf32.tf32.f32 "
                        "{%0,%1,%2,%3},{%4,%5,%6,%7},{%8,%9},{%0,%1,%2,%3};"
                        : "+f"(c[mf][nf][0]), "+f"(c[mf][nf][1]),
                          "+f"(c[mf][nf][2]), "+f"(c[mf][nf][3])
                        : "r"(a[mf][0]), "r"(a[mf][1]), "r"(a[mf][2]), "r"(a[mf][3]),
                          "r"(bf[nf][0]), "r"(bf[nf][1]));
        }
        __syncthreads();
    }
#pragma unroll
    for (int mf = 0; mf < 2; mf++)
#pragma unroll
        for (int nf = 0; nf < 4; nf++) {
            int row = m0 + wm + mf * 16 + gi;
            int col = n0 + wn + nf * 8 + ti * 2;
            *(float2*)&d_Kc[(size_t)row * 512 + col] = make_float2(c[mf][nf][0], c[mf][nf][1]);
            *(float2*)&d_Kc[(size_t)(row + 8) * 512 + col] = make_float2(c[mf][nf][2], c[mf][nf][3]);
        }
}

// ---------------- per-iteration kernels ----------------
__global__ void gru_kernel(const float* __restrict__ Wih1, const float* __restrict__ Whh1,
                           const float* __restrict__ bih1, const float* __restrict__ bhh1,
                           const float* __restrict__ Wih2, const float* __restrict__ Whh2,
                           const float* __restrict__ bih2, const float* __restrict__ bhh2) {
    int b = blockIdx.x, r = blockIdx.y, t = threadIdx.x;   // 384 threads
    const float* Wih = r ? Wih2 : Wih1;
    const float* Whh = r ? Whh2 : Whh1;
    const float* bih = r ? bih2 : bih1;
    const float* bhh = r ? bhh2 : bhh1;
    float* q = r ? d_q2 : d_q1;
    const float* iq = r ? d_iq2 : d_iq1;

    __shared__ __align__(16) float sx[E], sh[E];
    __shared__ float gi[3 * E], gh[3 * E];
    if (t < E) { sx[t] = iq[b * E + t]; sh[t] = q[b * E + t]; }
    __syncthreads();

    float a = bih[t], cgh = bhh[t];
    const float4* wi = (const float4*)(Wih + t * E);
    const float4* wh = (const float4*)(Whh + t * E);
    const float4* x4 = (const float4*)sx;
    const float4* h4 = (const float4*)sh;
#pragma unroll 8
    for (int e4 = 0; e4 < E / 4; e4++) {
        float4 wa = wi[e4], wb = wh[e4], xv = x4[e4], hv = h4[e4];
        a = fmaf(wa.x, xv.x, a); a = fmaf(wa.y, xv.y, a);
        a = fmaf(wa.z, xv.z, a); a = fmaf(wa.w, xv.w, a);
        cgh = fmaf(wb.x, hv.x, cgh); cgh = fmaf(wb.y, hv.y, cgh);
        cgh = fmaf(wb.z, hv.z, cgh); cgh = fmaf(wb.w, hv.w, cgh);
    }
    gi[t] = a; gh[t] = cgh;
    __syncthreads();
    if (t < E) {
        float rr = sigmoidf_(gi[t] + gh[t]);
        float z  = sigmoidf_(gi[E + t] + gh[E + t]);
        float n  = tanhf(gi[2 * E + t] + rr * gh[2 * E + t]);
        q[b * E + t] = (1.0f - z) * n + z * sh[t];
    }
}

__global__ void qproj_kernel(const float* __restrict__ WQ1, const float* __restrict__ WQ2,
                             const float* __restrict__ WQ3, const float* __restrict__ WQ4) {
    int b = blockIdx.x, t = threadIdx.x;                    // 512 threads
    __shared__ __align__(16) float s1[E], s2[E];
    if (t < E) s1[t] = d_q1[b * E + t];
    else if (t < 2 * E) s2[t - E] = d_q2[b * E + t - E];
    __syncthreads();
    int j = t >> 7, f = t & 127;
    const float* W = (j == 0) ? WQ1 : (j == 1) ? WQ2 : (j == 2) ? WQ3 : WQ4;
    const float4* w = (const float4*)(W + f * E);
    const float4* x = (const float4*)((j == 0 || j == 2) ? s1 : s2);
    float acc = 0.f;
#pragma unroll 8
    for (int e4 = 0; e4 < E / 4; e4++) {
        float4 a = w[e4], v = x[e4];
        acc = fmaf(a.x, v.x, acc); acc = fmaf(a.y, v.y, acc);
        acc = fmaf(a.z, v.z, acc); acc = fmaf(a.w, v.w, acc);
    }
    d_Qp[b * 512 + t] = acc;
}

__global__ void __launch_bounds__(256) score_kernel(int iter, const int* __restrict__ last_action,
                                                    const float* __restrict__ V1,
                                                    const float* __restrict__ V2) {
    int b = blockIdx.x, t = threadIdx.x;
    int warp = t >> 5, lane = t & 31;
    __shared__ float sQ[512];
    __shared__ float sV[256];
    sQ[t] = d_Qp[b * 512 + t];
    sQ[256 + t] = d_Qp[b * 512 + 256 + t];
    sV[t] = (t < 128) ? V1[t] : V2[t - 128];
    __syncthreads();

    int g = blockIdx.y * 8 + warp;
    const float* __restrict__ Kc = d_Kc + ((size_t)b * GS + g) * 512;
    float s = 0.f;
#pragma unroll
    for (int k = 0; k < 4; k++) {
        int f = lane + 32 * k;
        float k1 = Kc[f], k2 = Kc[128 + f], k3 = Kc[256 + f], k4 = Kc[384 + f];
        float a1 = fmaf(k3, sQ[256 + f], k1 + sQ[f]);
        float a2 = fmaf(k4, sQ[384 + f], k2 + sQ[128 + f]);
        s = fmaf(sV[f], tanh_fast(a1), s);
        s = fmaf(sV[128 + f], tanh_fast(a2), s);
    }
#pragma unroll
    for (int o = 16; o; o >>= 1) s += __shfl_xor_sync(0xFFFFFFFFu, s, o);
    if (lane == 0) {
        float lgt = tanhf(s) * CLIPV;
        bool m = (iter == 0) ? (g == last_action[b]) : (d_mask[b * GS + g] != 0);
        d_logits[b * GS + g] = m ? NEGV : lgt;
    }
}

__global__ void __launch_bounds__(256) update_kernel(int iter, const int* __restrict__ rec,
                                                     const int* __restrict__ vt,
                                                     const float* __restrict__ h,
                                                     const int* __restrict__ fixed_action) {
    int b = blockIdx.x, t = threadIdx.x;   // 256 threads, one block per b
    __shared__ float rbuf[8];
    __shared__ float s_max, s_lse;
    __shared__ int s_action, s_stopold, s_stopnew, s_nolmod, s_allow, s_ai0;

    const float* lg = d_logits + b * GS;
    const int bG = b * GS;

    // snapshot old scalars BEFORE any sync/writes
    int stop_old = d_stopped[b];
    int nol_old  = d_nol[b];
    int ai0_old  = d_ai[b * 4];
    int action   = (iter > 0 && stop_old) ? ai0_old : fixed_action[b * KM + iter];

    // --- max reduce ---
    float mx = -3.0e38f;
    for (int g = t; g < GS; g += 256) mx = fmaxf(mx, lg[g]);
#pragma unroll
    for (int o = 16; o; o >>= 1) mx = fmaxf(mx, __shfl_xor_sync(0xFFFFFFFFu, mx, o));
    if ((t & 31) == 0) rbuf[t >> 5] = mx;
    __syncthreads();
    if (t == 0) {
        float m = rbuf[0];
#pragma unroll
        for (int i = 1; i < 8; i++) m = fmaxf(m, rbuf[i]);
        s_max = m;
    }
    __syncthreads();
    float mm = s_max;

    // --- sum exp reduce ---
    float sum = 0.f;
    for (int g = t; g < GS; g += 256) sum += expf(lg[g] - mm);
#pragma unroll
    for (int o = 16; o; o >>= 1) sum += __shfl_xor_sync(0xFFFFFFFFu, sum, o);
    if ((t & 31) == 0) rbuf[t >> 5] = sum;
    __syncthreads();

    if (t == 0) {
        float tot = 0.f;
#pragma unroll
        for (int i = 0; i < 8; i++) tot += rbuf[i];
        s_lse = logf(tot);

        float loss = lg[action] - (mm + s_lse);
        if (iter == 0) d_ll[b] += loss;
        else if (!stop_old) d_ll[b] += loss;

        int nna = rec[bG + action];
        d_ai[b * 4 + iter] = action;
        if (stop_old) d_kl[b * 5 + iter] = action;
        int krm1 = ((iter - 1) + KM) % KM;
        if (!stop_old) d_kr[b * 4 + krm1] = action;
        d_kl[b * 5 + iter + 1] = nna;

        int eq = (action == nol_old) ? 1 : 0;
        int stop_new = (iter == 0) ? eq : (stop_old | eq);
        if (stop_new) {
            int klm1 = ((iter - 1) + 5) % 5;
            d_kl[b * 5 + iter] = d_kl[b * 5 + klm1];
            d_kr[b * 4 + iter] = d_kr[b * 4 + krm1];
        }
        d_stopped[b] = stop_new;
        d_nol[b] = stop_new ? -1 : nna;

        int ai0 = (iter == 0) ? action : ai0_old;
        s_action = action;
        s_stopold = stop_old;
        s_stopnew = stop_new;
        s_nolmod = ((nol_old % GS) + GS) % GS;   // Python floored mod
        s_ai0 = ai0;
        s_allow = (!stop_new && nna == ai0) ? 1 : 0;
    }
    __syncthreads();

    int act = s_action;
    int va = (iter == 0) ? 0 : d_vtt[bG + act];
    int vta = (iter == 0) ? vt[bG + act] : 0;
    for (int g = t; g < GS; g += 256) {
        int v;
        if (iter == 0) {
            v = (((vt[bG + g] - vta) % GS) + GS) % GS;
            d_vtt[bG + g] = v;
        } else {
            v = d_vtt[bG + g];
        }
        bool m = (v <= va);
        if (iter == 0) m = m || (v > GS - 2);
        if (s_stopnew && g == act) m = false;
        if (s_allow && g == s_ai0) m = false;
        d_mask[bG + g] = m ? 1 : 0;
    }

    if (t < E) {
        float hq1 = h[((size_t)bG + act) * E + t];
        d_iq1[b * E + t] = hq1;
        d_iq2[b * E + t] = s_stopold ? hq1 : h[((size_t)bG + s_nolmod) * E + t];
    }
}

// ---------------- output ----------------
__global__ void out_kernel(float* __restrict__ out) {
    int idx = blockIdx.x * 256 + threadIdx.x;
    if (idx < BS * 12) {
        int b = idx / 12, j = idx % 12;
        int v;
        if (j < 4) v = d_ai[b * 4 + j];
        else if (j < 8) v = d_kl[b * 5 + (j - 4)];
        else {
            int jj = j - 8;
            if (jj == 3 && !d_stopped[b]) v = d_kl[b * 5 + 4];  // post-loop kr fix
            else v = d_kr[b * 4 + jj];
        }
        out[idx] = (float)v;
    } else if (idx < BS * 12 + BS) {
        out[idx] = d_ll[idx - BS * 12];
    }
}

// ---------------- launch ----------------
extern "C" void kernel_launch(void* const* d_in, const int* in_sizes, int n_in,
                              void* d_out, int out_size) {
    (void)in_sizes; (void)n_in; (void)out_size;
    const float* h            = (const float*)d_in[0];
    const int*   rec          = (const int*)  d_in[1];
    /* context2 d_in[2] unused */
    const int*   visited_time = (const int*)  d_in[3];
    const int*   last_action  = (const int*)  d_in[4];
    const int*   fixed_action = (const int*)  d_in[5];
    const float* W_K1 = (const float*)d_in[6];
    const float* W_K2 = (const float*)d_in[7];
    const float* W_K3 = (const float*)d_in[8];
    const float* W_K4 = (const float*)d_in[9];
    const float* W_Q1 = (const float*)d_in[10];
    const float* W_Q2 = (const float*)d_in[11];
    const float* W_Q3 = (const float*)d_in[12];
    const float* W_Q4 = (const float*)d_in[13];
    const float* W_init     = (const float*)d_in[14];
    const float* b_init     = (const float*)d_in[15];
    const float* V1         = (const float*)d_in[16];
    const float* V2         = (const float*)d_in[17];
    const float* init_query = (const float*)d_in[18];
    const float* r1_Wih = (const float*)d_in[19];
    const float* r1_Whh = (const float*)d_in[20];
    const float* r1_bih = (const float*)d_in[21];
    const float* r1_bhh = (const float*)d_in[22];
    const float* r2_Wih = (const float*)d_in[23];
    const float* r2_Whh = (const float*)d_in[24];
    const float* r2_bih = (const float*)d_in[25];
    const float* r2_bhh = (const float*)d_in[26];

    transpose_w<<<256, 256>>>(W_K1, W_K2, W_K3, W_K4);
    hmean_kernel<<<BS, 512>>>(h);
    init_kernel<<<BS, 128>>>(W_init, b_init, init_query);
    gemm_kernel<<<dim3(4000, 8), 128>>>(h);

    for (int i = 0; i < KM; i++) {
        gru_kernel<<<dim3(BS, 2), 384>>>(r1_Wih, r1_Whh, r1_bih, r1_bhh,
                                         r2_Wih, r2_Whh, r2_bih, r2_bhh);
        qproj_kernel<<<BS, 512>>>(W_Q1, W_Q2, W_Q3, W_Q4);
        score_kernel<<<dim3(BS, 250), 256>>>(i, last_action, V1, V2);
        update_kernel<<<BS, 256>>>(i, rec, visited_time, h, fixed_action);
    }
    out_kernel<<<7, 256>>>((float*)d_out);
}

// round 7
// speedup vs baseline: 1.1809x; 1.1809x over previous
#include <cuda_runtime.h>
#include <cuda_bf16.h>
#include <math.h>
#include <stdint.h>

#define BS   128
#define GS   2000
#define E    128
#define KM   4
#define NEGV (-1.0e30f)
#define CLIPV 10.0f

// ---------------- device scratch (static globals; no runtime allocation) ----------------
__device__ __nv_bfloat16 d_Kcb[(size_t)BS * GS * 512];  // [b][g][K1|K2|K3|K4] bf16 (262 MB)
__device__ __nv_bfloat16 d_Wb[512 * 128];               // [n=j*128+f][k=e] bf16 (= W_Kj rows, col-major B)
__device__ float d_logits[BS * GS];
__device__ unsigned char d_mask[BS * GS];
__device__ int   d_vtt[BS * GS];
__device__ float d_q1[BS * E], d_q2[BS * E];
__device__ float d_iq1[BS * E], d_iq2[BS * E];
__device__ float d_Qp[BS * 512];                        // [Q1|Q2|Q3|Q4] per b
__device__ float d_hmean[BS * E];
__device__ int   d_ai[BS * 4];
__device__ int   d_kl[BS * 5];
__device__ int   d_kr[BS * 4];
__device__ int   d_nol[BS];
__device__ int   d_stopped[BS];
__device__ float d_ll[BS];

// ---------------- math helpers (no MUFU in hot path) ----------------
__device__ __forceinline__ float fast_rcp(float x) {
    float r = __uint_as_float(0x7EF311C3u - __float_as_uint(x));
    r = r * (2.0f - x * r);
    r = r * (2.0f - x * r);
    return r;
}
__device__ __forceinline__ float tanh_fast(float x) {
    // Pade(5,4), clamp 3.6; abs err <= ~1e-3; fma/alu pipes only
    float xc = fminf(fmaxf(x, -3.6f), 3.6f);
    float x2 = xc * xc;
    float num = xc * fmaf(x2, x2 + 105.0f, 945.0f);
    float den = fmaf(x2, fmaf(15.0f, x2, 420.0f), 945.0f);
    return num * fast_rcp(den);
}
__device__ __forceinline__ float sigmoidf_(float x) { return 1.0f / (1.0f + expf(-x)); }

// ---------------- setup kernels ----------------
__global__ void convert_w(const float* __restrict__ W1, const float* __restrict__ W2,
                          const float* __restrict__ W3, const float* __restrict__ W4) {
    // B matrix for mma row.col: col-major k x n == W_Kj[f][e] rows as stored. Just bf16-copy.
    int idx = blockIdx.x * blockDim.x + threadIdx.x;    // 65536
    if (idx >= 512 * 128) return;
    int j = idx >> 14, r = idx & 16383;
    const float* W = (j == 0) ? W1 : (j == 1) ? W2 : (j == 2) ? W3 : W4;
    d_Wb[idx] = __float2bfloat16(W[r]);
}

__global__ void hmean_kernel(const float* __restrict__ h) {
    int b = blockIdx.x, t = threadIdx.x;                 // 512 threads
    int e = t & 127, q = t >> 7;
    __shared__ float part[4][128];
    float s = 0.f;
    for (int g = q * 500; g < (q + 1) * 500; g++)
        s += h[((size_t)b * GS + g) * E + e];
    part[q][e] = s;
    __syncthreads();
    if (t < 128)
        d_hmean[b * E + t] = (part[0][t] + part[1][t] + part[2][t] + part[3][t]) * (1.0f / GS);
}

__global__ void init_kernel(const float* __restrict__ W_init, const float* __restrict__ b_init,
                            const float* __restrict__ init_query) {
    int b = blockIdx.x, t = threadIdx.x;                 // 128 threads
    __shared__ __align__(16) float sm[E];
    sm[t] = d_hmean[b * E + t];
    __syncthreads();
    float acc = b_init[t];
    const float4* w = (const float4*)(W_init + t * E);
    const float4* x = (const float4*)sm;
#pragma unroll 8
    for (int e4 = 0; e4 < E / 4; e4++) {
        float4 a = w[e4], v = x[e4];
        acc = fmaf(a.x, v.x, acc); acc = fmaf(a.y, v.y, acc);
        acc = fmaf(a.z, v.z, acc); acc = fmaf(a.w, v.w, acc);
    }
    d_q1[b * E + t] = acc;
    d_q2[b * E + t] = acc;
    float iq = init_query[t];
    d_iq1[b * E + t] = iq;
    d_iq2[b * E + t] = iq;
    if (t == 0) { d_stopped[b] = 1; d_nol[b] = -1; d_ll[b] = 0.0f; }
    if (t < 5) d_kl[b * 5 + t] = 0;
    if (t < 4) { d_ai[b * 4 + t] = 0; d_kr[b * 4 + t] = 0; }
}

// ---------------- bf16 MMA GEMM: Kcb[256000,512] = h[256000,128] @ W^T ----------------
// Block: 128 threads, tile m=64 n=64, full K=128 resident in smem (no k reload).
__global__ void __launch_bounds__(128) gemm_kernel(const float* __restrict__ A) {
    __shared__ __nv_bfloat16 As[64][136];   // [m][k], pad 8 -> conflict-free frag reads
    __shared__ __nv_bfloat16 Bs[64][136];   // [n][k] (col-major B)
    const int t = threadIdx.x;
    const int warp = t >> 5, lane = t & 31;
    const int m0 = blockIdx.x * 64, n0 = blockIdx.y * 64;
    const int wm = (warp >> 1) * 32, wn = (warp & 1) * 32;
    const int qr = lane >> 2, qc = lane & 3;

    // load A: 64 rows x 128 k fp32 -> bf16 (each thread 16 float4)
#pragma unroll
    for (int i = t; i < 64 * 32; i += 128) {
        int row = i >> 5, c4 = i & 31;
        float4 v = *(const float4*)(A + (size_t)(m0 + row) * 128 + c4 * 4);
        __nv_bfloat162 lo = __floats2bfloat162_rn(v.x, v.y);
        __nv_bfloat162 hi = __floats2bfloat162_rn(v.z, v.w);
        uint2 pk = make_uint2(*(unsigned*)&lo, *(unsigned*)&hi);
        *(uint2*)&As[row][c4 * 4] = pk;
    }
    // load B: 64 n x 128 k bf16, straight copy (each thread 8 uint4)
#pragma unroll
    for (int i = t; i < 64 * 16; i += 128) {
        int n = i >> 4, c8 = i & 15;
        *(uint4*)&Bs[n][c8 * 8] = *(const uint4*)(d_Wb + (size_t)(n0 + n) * 128 + c8 * 8);
    }
    __syncthreads();

    float c[2][4][4];
#pragma unroll
    for (int i = 0; i < 2; i++)
#pragma unroll
        for (int j = 0; j < 4; j++)
#pragma unroll
            for (int k = 0; k < 4; k++) c[i][j][k] = 0.f;

#pragma unroll
    for (int ks = 0; ks < 8; ks++) {
        int kk = ks * 16;
        unsigned a[2][4], bf[4][2];
#pragma unroll
        for (int mf = 0; mf < 2; mf++) {
            int r = wm + mf * 16 + qr;
            a[mf][0] = *(unsigned*)&As[r][kk + qc * 2];
            a[mf][1] = *(unsigned*)&As[r + 8][kk + qc * 2];
            a[mf][2] = *(unsigned*)&As[r][kk + 8 + qc * 2];
            a[mf][3] = *(unsigned*)&As[r + 8][kk + 8 + qc * 2];
        }
#pragma unroll
        for (int nf = 0; nf < 4; nf++) {
            int n = wn + nf * 8 + qr;
            bf[nf][0] = *(unsigned*)&Bs[n][kk + qc * 2];
            bf[nf][1] = *(unsigned*)&Bs[n][kk + 8 + qc * 2];
        }
#pragma unroll
        for (int mf = 0; mf < 2; mf++)
#pragma unroll
            for (int nf = 0; nf < 4; nf++)
                asm volatile(
                    "mma.sync.aligned.m16n8k16.row.col.f32.bf16.bf16.f32 "
                    "{%0,%1,%2,%3},{%4,%5,%6,%7},{%8,%9},{%0,%1,%2,%3};"
                    : "+f"(c[mf][nf][0]), "+f"(c[mf][nf][1]),
                      "+f"(c[mf][nf][2]), "+f"(c[mf][nf][3])
                    : "r"(a[mf][0]), "r"(a[mf][1]), "r"(a[mf][2]), "r"(a[mf][3]),
                      "r"(bf[nf][0]), "r"(bf[nf][1]));
    }

    // epilogue: bf16 store
#pragma unroll
    for (int mf = 0; mf < 2; mf++)
#pragma unroll
        for (int nf = 0; nf < 4; nf++) {
            int row = m0 + wm + mf * 16 + qr;
            int col = n0 + wn + nf * 8 + qc * 2;
            __nv_bfloat162 v0 = __floats2bfloat162_rn(c[mf][nf][0], c[mf][nf][1]);
            __nv_bfloat162 v1 = __floats2bfloat162_rn(c[mf][nf][2], c[mf][nf][3]);
            *(__nv_bfloat162*)&d_Kcb[(size_t)row * 512 + col] = v0;
            *(__nv_bfloat162*)&d_Kcb[(size_t)(row + 8) * 512 + col] = v1;
        }
}

// ---------------- per-iteration kernels ----------------
__global__ void gru_kernel(const float* __restrict__ Wih1, const float* __restrict__ Whh1,
                           const float* __restrict__ bih1, const float* __restrict__ bhh1,
                           const float* __restrict__ Wih2, const float* __restrict__ Whh2,
                           const float* __restrict__ bih2, const float* __restrict__ bhh2) {
    int b = blockIdx.x, r = blockIdx.y, t = threadIdx.x;   // 384 threads
    const float* Wih = r ? Wih2 : Wih1;
    const float* Whh = r ? Whh2 : Whh1;
    const float* bih = r ? bih2 : bih1;
    const float* bhh = r ? bhh2 : bhh1;
    float* q = r ? d_q2 : d_q1;
    const float* iq = r ? d_iq2 : d_iq1;

    __shared__ __align__(16) float sx[E], sh[E];
    __shared__ float gi[3 * E], gh[3 * E];
    if (t < E) { sx[t] = iq[b * E + t]; sh[t] = q[b * E + t]; }
    __syncthreads();

    float a = bih[t], cgh = bhh[t];
    const float4* wi = (const float4*)(Wih + t * E);
    const float4* wh = (const float4*)(Whh + t * E);
    const float4* x4 = (const float4*)sx;
    const float4* h4 = (const float4*)sh;
#pragma unroll 8
    for (int e4 = 0; e4 < E / 4; e4++) {
        float4 wa = wi[e4], wb = wh[e4], xv = x4[e4], hv = h4[e4];
        a = fmaf(wa.x, xv.x, a); a = fmaf(wa.y, xv.y, a);
        a = fmaf(wa.z, xv.z, a); a = fmaf(wa.w, xv.w, a);
        cgh = fmaf(wb.x, hv.x, cgh); cgh = fmaf(wb.y, hv.y, cgh);
        cgh = fmaf(wb.z, hv.z, cgh); cgh = fmaf(wb.w, hv.w, cgh);
    }
    gi[t] = a; gh[t] = cgh;
    __syncthreads();
    if (t < E) {
        float rr = sigmoidf_(gi[t] + gh[t]);
        float z  = sigmoidf_(gi[E + t] + gh[E + t]);
        float n  = tanhf(gi[2 * E + t] + rr * gh[2 * E + t]);
        q[b * E + t] = (1.0f - z) * n + z * sh[t];
    }
}

__global__ void qproj_kernel(const float* __restrict__ WQ1, const float* __restrict__ WQ2,
                             const float* __restrict__ WQ3, const float* __restrict__ WQ4) {
    int b = blockIdx.x, t = threadIdx.x;                    // 512 threads
    __shared__ __align__(16) float s1[E], s2[E];
    if (t < E) s1[t] = d_q1[b * E + t];
    else if (t < 2 * E) s2[t - E] = d_q2[b * E + t - E];
    __syncthreads();
    int j = t >> 7, f = t & 127;
    const float* W = (j == 0) ? WQ1 : (j == 1) ? WQ2 : (j == 2) ? WQ3 : WQ4;
    const float4* w = (const float4*)(W + f * E);
    const float4* x = (const float4*)((j == 0 || j == 2) ? s1 : s2);
    float acc = 0.f;
#pragma unroll 8
    for (int e4 = 0; e4 < E / 4; e4++) {
        float4 a = w[e4], v = x[e4];
        acc = fmaf(a.x, v.x, acc); acc = fmaf(a.y, v.y, acc);
        acc = fmaf(a.z, v.z, acc); acc = fmaf(a.w, v.w, acc);
    }
    d_Qp[b * 512 + t] = acc;
}

__global__ void __launch_bounds__(256) score_kernel(int iter, const int* __restrict__ last_action,
                                                    const float* __restrict__ V1,
                                                    const float* __restrict__ V2) {
    int b = blockIdx.x, t = threadIdx.x;
    int warp = t >> 5, lane = t & 31;
    __shared__ float sQ[512];
    __shared__ float sV[256];
    sQ[t] = d_Qp[b * 512 + t];
    sQ[256 + t] = d_Qp[b * 512 + 256 + t];
    sV[t] = (t < 128) ? V1[t] : V2[t - 128];
    __syncthreads();

    int g = blockIdx.y * 8 + warp;
    const __nv_bfloat16* __restrict__ Kc = d_Kcb + ((size_t)b * GS + g) * 512;
    // lane handles f = lane*4 + {0..3} in each 128-wide segment; 8B coalesced loads
    int f0 = lane * 4;
    uint2 u1 = *(const uint2*)(Kc + f0);
    uint2 u2 = *(const uint2*)(Kc + 128 + f0);
    uint2 u3 = *(const uint2*)(Kc + 256 + f0);
    uint2 u4 = *(const uint2*)(Kc + 384 + f0);
    float s = 0.f;
#pragma unroll
    for (int half = 0; half < 2; half++) {
        unsigned w1 = half ? u1.y : u1.x;
        unsigned w2 = half ? u2.y : u2.x;
        unsigned w3 = half ? u3.y : u3.x;
        unsigned w4 = half ? u4.y : u4.x;
        float2 k1 = __bfloat1622float2(*(__nv_bfloat162*)&w1);
        float2 k2 = __bfloat1622float2(*(__nv_bfloat162*)&w2);
        float2 k3 = __bfloat1622float2(*(__nv_bfloat162*)&w3);
        float2 k4 = __bfloat1622float2(*(__nv_bfloat162*)&w4);
#pragma unroll
        for (int i = 0; i < 2; i++) {
            int f = f0 + half * 2 + i;
            float k1v = i ? k1.y : k1.x, k2v = i ? k2.y : k2.x;
            float k3v = i ? k3.y : k3.x, k4v = i ? k4.y : k4.x;
            float a1 = fmaf(k3v, sQ[256 + f], k1v + sQ[f]);
            float a2 = fmaf(k4v, sQ[384 + f], k2v + sQ[128 + f]);
            s = fmaf(sV[f], tanh_fast(a1), s);
            s = fmaf(sV[128 + f], tanh_fast(a2), s);
        }
    }
#pragma unroll
    for (int o = 16; o; o >>= 1) s += __shfl_xor_sync(0xFFFFFFFFu, s, o);
    if (lane == 0) {
        float lgt = tanhf(s) * CLIPV;
        bool m = (iter == 0) ? (g == last_action[b]) : (d_mask[b * GS + g] != 0);
        d_logits[b * GS + g] = m ? NEGV : lgt;
    }
}

__global__ void __launch_bounds__(256) update_kernel(int iter, const int* __restrict__ rec,
                                                     const int* __restrict__ vt,
                                                     const float* __restrict__ h,
                                                     const int* __restrict__ fixed_action) {
    int b = blockIdx.x, t = threadIdx.x;   // 256 threads, one block per b
    __shared__ float rbuf[8];
    __shared__ float s_max;
    __shared__ int s_action, s_stopold, s_stopnew, s_nolmod, s_allow, s_ai0;

    const float* lg = d_logits + b * GS;
    const int bG = b * GS;

    int stop_old = d_stopped[b];
    int nol_old  = d_nol[b];
    int ai0_old  = d_ai[b * 4];
    int action   = (iter > 0 && stop_old) ? ai0_old : fixed_action[b * KM + iter];

    // --- max reduce ---
    float mx = -3.0e38f;
    for (int g = t; g < GS; g += 256) mx = fmaxf(mx, lg[g]);
#pragma unroll
    for (int o = 16; o; o >>= 1) mx = fmaxf(mx, __shfl_xor_sync(0xFFFFFFFFu, mx, o));
    if ((t & 31) == 0) rbuf[t >> 5] = mx;
    __syncthreads();
    if (t == 0) {
        float m = rbuf[0];
#pragma unroll
        for (int i = 1; i < 8; i++) m = fmaxf(m, rbuf[i]);
        s_max = m;
    }
    __syncthreads();
    float mm = s_max;

    // --- sum exp reduce ---
    float sum = 0.f;
    for (int g = t; g < GS; g += 256) sum += expf(lg[g] - mm);
#pragma unroll
    for (int o = 16; o; o >>= 1) sum += __shfl_xor_sync(0xFFFFFFFFu, sum, o);
    if ((t & 31) == 0) rbuf[t >> 5] = sum;
    __syncthreads();

    if (t == 0) {
        float tot = 0.f;
#pragma unroll
        for (int i = 0; i < 8; i++) tot += rbuf[i];

        float loss = lg[action] - (mm + logf(tot));
        if (iter == 0) d_ll[b] += loss;
        else if (!stop_old) d_ll[b] += loss;

        int nna = rec[bG + action];
        d_ai[b * 4 + iter] = action;
        if (stop_old) d_kl[b * 5 + iter] = action;
        int krm1 = ((iter - 1) + KM) % KM;
        if (!stop_old) d_kr[b * 4 + krm1] = action;
        d_kl[b * 5 + iter + 1] = nna;

        int eq = (action == nol_old) ? 1 : 0;
        int stop_new = (iter == 0) ? eq : (stop_old | eq);
        if (stop_new) {
            int klm1 = ((iter - 1) + 5) % 5;
            d_kl[b * 5 + iter] = d_kl[b * 5 + klm1];
            d_kr[b * 4 + iter] = d_kr[b * 4 + krm1];
        }
        d_stopped[b] = stop_new;
        d_nol[b] = stop_new ? -1 : nna;

        int ai0 = (iter == 0) ? action : ai0_old;
        s_action = action;
        s_stopold = stop_old;
        s_stopnew = stop_new;
        s_nolmod = ((nol_old % GS) + GS) % GS;   // Python floored mod
        s_ai0 = ai0;
        s_allow = (!stop_new && nna == ai0) ? 1 : 0;
    }
    __syncthreads();

    int act = s_action;
    int va = (iter == 0) ? 0 : d_vtt[bG + act];
    int vta = (iter == 0) ? vt[bG + act] : 0;
    for (int g = t; g < GS; g += 256) {
        int v;
        if (iter == 0) {
            v = (((vt[bG + g] - vta) % GS) + GS) % GS;
            d_vtt[bG + g] = v;
        } else {
            v = d_vtt[bG + g];
        }
        bool m = (v <= va);
        if (iter == 0) m = m || (v > GS - 2);
        if (s_stopnew && g == act) m = false;
        if (s_allow && g == s_ai0) m = false;
        d_mask[bG + g] = m ? 1 : 0;
    }

    if (t < E) {
        float hq1 = h[((size_t)bG + act) * E + t];
        d_iq1[b * E + t] = hq1;
        d_iq2[b * E + t] = s_stopold ? hq1 : h[((size_t)bG + s_nolmod) * E + t];
    }
}

// ---------------- output ----------------
__global__ void out_kernel(float* __restrict__ out) {
    int idx = blockIdx.x * 256 + threadIdx.x;
    if (idx < BS * 12) {
        int b = idx / 12, j = idx % 12;
        int v;
        if (j < 4) v = d_ai[b * 4 + j];
        else if (j < 8) v = d_kl[b * 5 + (j - 4)];
        else {
            int jj = j - 8;
            if (jj == 3 && !d_stopped[b]) v = d_kl[b * 5 + 4];  // post-loop kr fix
            else v = d_kr[b * 4 + jj];
        }
        out[idx] = (float)v;
    } else if (idx < BS * 12 + BS) {
        out[idx] = d_ll[idx - BS * 12];
    }
}

// ---------------- launch ----------------
extern "C" void kernel_launch(void* const* d_in, const int* in_sizes, int n_in,
                              void* d_out, int out_size) {
    (void)in_sizes; (void)n_in; (void)out_size;
    const float* h            = (const float*)d_in[0];
    const int*   rec          = (const int*)  d_in[1];
    /* context2 d_in[2] unused */
    const int*   visited_time = (const int*)  d_in[3];
    const int*   last_action  = (const int*)  d_in[4];
    const int*   fixed_action = (const int*)  d_in[5];
    const float* W_K1 = (const float*)d_in[6];
    const float* W_K2 = (const float*)d_in[7];
    const float* W_K3 = (const float*)d_in[8];
    const float* W_K4 = (const float*)d_in[9];
    const float* W_Q1 = (const float*)d_in[10];
    const float* W_Q2 = (const float*)d_in[11];
    const float* W_Q3 = (const float*)d_in[12];
    const float* W_Q4 = (const float*)d_in[13];
    const float* W_init     = (const float*)d_in[14];
    const float* b_init     = (const float*)d_in[15];
    const float* V1         = (const float*)d_in[16];
    const float* V2         = (const float*)d_in[17];
    const float* init_query = (const float*)d_in[18];
    const float* r1_Wih = (const float*)d_in[19];
    const float* r1_Whh = (const float*)d_in[20];
    const float* r1_bih = (const float*)d_in[21];
    const float* r1_bhh = (const float*)d_in[22];
    const float* r2_Wih = (const float*)d_in[23];
    const float* r2_Whh = (const float*)d_in[24];
    const float* r2_bih = (const float*)d_in[25];
    const float* r2_bhh = (const float*)d_in[26];

    convert_w<<<256, 256>>>(W_K1, W_K2, W_K3, W_K4);
    hmean_kernel<<<BS, 512>>>(h);
    init_kernel<<<BS, 128>>>(W_init, b_init, init_query);
    gemm_kernel<<<dim3(4000, 8), 128>>>(h);

    for (int i = 0; i < KM; i++) {
        gru_kernel<<<dim3(BS, 2), 384>>>(r1_Wih, r1_Whh, r1_bih, r1_bhh,
                                         r2_Wih, r2_Whh, r2_bih, r2_bhh);
        qproj_kernel<<<BS, 512>>>(W_Q1, W_Q2, W_Q3, W_Q4);
        score_kernel<<<dim3(BS, 250), 256>>>(i, last_action, V1, V2);
        update_kernel<<<BS, 256>>>(i, rec, visited_time, h, fixed_action);
    }
    out_kernel<<<7, 256>>>((float*)d_out);
}

// round 9
// speedup vs baseline: 1.2787x; 1.0828x over previous
#include <cuda_runtime.h>
#include <cuda_bf16.h>
#include <cuda_fp16.h>
#include <math.h>
#include <stdint.h>

#define BS   128
#define GS   2000
#define E    128
#define KM   4
#define NEGV (-1.0e30f)
#define CLIPV 10.0f

// ---------------- device scratch (static globals; no runtime allocation) ----------------
__device__ unsigned char d_Kc8[(size_t)BS * GS * 512];  // [b][g][K1|K2|K3|K4] e4m3 (131 MB)
__device__ __nv_bfloat16 d_Wb[512 * 128];               // [n=j*128+f][k=e] bf16 (col-major B)
__device__ float d_logits[BS * GS];
__device__ float d_expsum[BS];
__device__ unsigned char d_mask[BS * GS];
__device__ int   d_vtt[BS * GS];
__device__ float d_q1[BS * E], d_q2[BS * E];
__device__ float d_iq1[BS * E], d_iq2[BS * E];
__device__ float d_Qp[BS * 512];                        // [Q1|Q2|Q3|Q4] per b
__device__ float d_hmean[BS * E];
__device__ int   d_ai[BS * 4];
__device__ int   d_kl[BS * 5];
__device__ int   d_kr[BS * 4];
__device__ int   d_nol[BS];
__device__ int   d_stopped[BS];
__device__ float d_ll[BS];

// ---------------- math helpers ----------------
__device__ __forceinline__ float fast_rcp(float x) {
    float r = __uint_as_float(0x7EF311C3u - __float_as_uint(x));
    r = r * (2.0f - x * r);
    r = r * (2.0f - x * r);
    return r;
}
__device__ __forceinline__ float tanh_fast(float x) {
    // Pade(5,4), clamp 3.6; abs err <= ~1e-3; fma/alu pipes only
    float xc = fminf(fmaxf(x, -3.6f), 3.6f);
    float x2 = xc * xc;
    float num = xc * fmaf(x2, x2 + 105.0f, 945.0f);
    float den = fmaf(x2, fmaf(15.0f, x2, 420.0f), 945.0f);
    return num * fast_rcp(den);
}
__device__ __forceinline__ float sigmoidf_(float x) { return 1.0f / (1.0f + expf(-x)); }

// pack two f32 -> e4m3x2 (byte0 = a, byte1 = b)
__device__ __forceinline__ unsigned short fp8pack(float a, float b) {
    unsigned short p;
    asm("cvt.rn.satfinite.e4m3x2.f32 %0, %1, %2;" : "=h"(p) : "f"(b), "f"(a));
    return p;
}
// 4 e4m3 bytes -> 4 floats (o[0] = byte0 ...)
__device__ __forceinline__ void fp8x4_to_f32(unsigned u, float* o) {
    unsigned h01, h23;
    asm("{\n\t.reg .b16 lo, hi;\n\t"
        "mov.b32 {lo, hi}, %2;\n\t"
        "cvt.rn.f16x2.e4m3x2 %0, lo;\n\t"
        "cvt.rn.f16x2.e4m3x2 %1, hi;\n\t}"
        : "=r"(h01), "=r"(h23) : "r"(u));
    float2 x = __half22float2(*reinterpret_cast<__half2*>(&h01));
    float2 y = __half22float2(*reinterpret_cast<__half2*>(&h23));
    o[0] = x.x; o[1] = x.y; o[2] = y.x; o[3] = y.y;
}

// ---------------- setup kernels ----------------
__global__ void convert_w(const float* __restrict__ W1, const float* __restrict__ W2,
                          const float* __restrict__ W3, const float* __restrict__ W4) {
    int idx = blockIdx.x * blockDim.x + threadIdx.x;    // 65536
    if (idx >= 512 * 128) return;
    int j = idx >> 14, r = idx & 16383;
    const float* W = (j == 0) ? W1 : (j == 1) ? W2 : (j == 2) ? W3 : W4;
    d_Wb[idx] = __float2bfloat16(W[r]);
}

__global__ void hmean_kernel(const float* __restrict__ h) {
    int b = blockIdx.x, t = threadIdx.x;                 // 512 threads
    int e = t & 127, q = t >> 7;
    __shared__ float part[4][128];
    float s = 0.f;
    for (int g = q * 500; g < (q + 1) * 500; g++)
        s += h[((size_t)b * GS + g) * E + e];
    part[q][e] = s;
    __syncthreads();
    if (t < 128)
        d_hmean[b * E + t] = (part[0][t] + part[1][t] + part[2][t] + part[3][t]) * (1.0f / GS);
}

__global__ void init_kernel(const float* __restrict__ W_init, const float* __restrict__ b_init,
                            const float* __restrict__ init_query) {
    int b = blockIdx.x, t = threadIdx.x;                 // 128 threads
    __shared__ __align__(16) float sm[E];
    sm[t] = d_hmean[b * E + t];
    __syncthreads();
    float acc = b_init[t];
    const float4* w = (const float4*)(W_init + t * E);
    const float4* x = (const float4*)sm;
#pragma unroll 8
    for (int e4 = 0; e4 < E / 4; e4++) {
        float4 a = w[e4], v = x[e4];
        acc = fmaf(a.x, v.x, acc); acc = fmaf(a.y, v.y, acc);
        acc = fmaf(a.z, v.z, acc); acc = fmaf(a.w, v.w, acc);
    }
    d_q1[b * E + t] = acc;
    d_q2[b * E + t] = acc;
    float iq = init_query[t];
    d_iq1[b * E + t] = iq;
    d_iq2[b * E + t] = iq;
    if (t == 0) { d_stopped[b] = 1; d_nol[b] = -1; d_ll[b] = 0.0f; }
    if (t < 5) d_kl[b * 5 + t] = 0;
    if (t < 4) { d_ai[b * 4 + t] = 0; d_kr[b * 4 + t] = 0; }
}

// ---------------- bf16 MMA GEMM: Kc8[256000,512] = e4m3(h[256000,128] @ W^T) ----------------
// grid (8_n, 4000_m): n varies fastest -> the 8 n-blocks sharing an A tile are
// schedule-adjacent, so A is read once from DRAM and 7x from L2.
__global__ void __launch_bounds__(128) gemm_kernel(const float* __restrict__ A) {
    __shared__ __nv_bfloat16 As[64][136];   // [m][k], pad -> conflict-free frag reads
    __shared__ __nv_bfloat16 Bs[64][136];   // [n][k] (col-major B)
    const int t = threadIdx.x;
    const int warp = t >> 5, lane = t & 31;
    const int n0 = blockIdx.x * 64, m0 = blockIdx.y * 64;
    const int wm = (warp >> 1) * 32, wn = (warp & 1) * 32;
    const int qr = lane >> 2, qc = lane & 3;

    // load A: 64 rows x 128 k fp32 -> bf16
#pragma unroll
    for (int i = t; i < 64 * 32; i += 128) {
        int row = i >> 5, c4 = i & 31;
        float4 v = *(const float4*)(A + (size_t)(m0 + row) * 128 + c4 * 4);
        __nv_bfloat162 lo = __floats2bfloat162_rn(v.x, v.y);
        __nv_bfloat162 hi = __floats2bfloat162_rn(v.z, v.w);
        uint2 pk = make_uint2(*(unsigned*)&lo, *(unsigned*)&hi);
        *(uint2*)&As[row][c4 * 4] = pk;
    }
    // load B: 64 n x 128 k bf16, straight copy
#pragma unroll
    for (int i = t; i < 64 * 16; i += 128) {
        int n = i >> 4, c8 = i & 15;
        *(uint4*)&Bs[n][c8 * 8] = *(const uint4*)(d_Wb + (size_t)(n0 + n) * 128 + c8 * 8);
    }
    __syncthreads();

    float c[2][4][4];
#pragma unroll
    for (int i = 0; i < 2; i++)
#pragma unroll
        for (int j = 0; j < 4; j++)
#pragma unroll
            for (int k = 0; k < 4; k++) c[i][j][k] = 0.f;

#pragma unroll
    for (int ks = 0; ks < 8; ks++) {
        int kk = ks * 16;
        unsigned a[2][4], bf[4][2];
#pragma unroll
        for (int mf = 0; mf < 2; mf++) {
            int r = wm + mf * 16 + qr;
            a[mf][0] = *(unsigned*)&As[r][kk + qc * 2];
            a[mf][1] = *(unsigned*)&As[r + 8][kk + qc * 2];
            a[mf][2] = *(unsigned*)&As[r][kk + 8 + qc * 2];
            a[mf][3] = *(unsigned*)&As[r + 8][kk + 8 + qc * 2];
        }
#pragma unroll
        for (int nf = 0; nf < 4; nf++) {
            int n = wn + nf * 8 + qr;
            bf[nf][0] = *(unsigned*)&Bs[n][kk + qc * 2];
            bf[nf][1] = *(unsigned*)&Bs[n][kk + 8 + qc * 2];
        }
#pragma unroll
        for (int mf = 0; mf < 2; mf++)
#pragma unroll
            for (int nf = 0; nf < 4; nf++)
                asm volatile(
                    "mma.sync.aligned.m16n8k16.row.col.f32.bf16.bf16.f32 "
                    "{%0,%1,%2,%3},{%4,%5,%6,%7},{%8,%9},{%0,%1,%2,%3};"
                    : "+f"(c[mf][nf][0]), "+f"(c[mf][nf][1]),
                      "+f"(c[mf][nf][2]), "+f"(c[mf][nf][3])
                    : "r"(a[mf][0]), "r"(a[mf][1]), "r"(a[mf][2]), "r"(a[mf][3]),
                      "r"(bf[nf][0]), "r"(bf[nf][1]));
    }

    // epilogue: e4m3 store (2 bytes per fragment row)
#pragma unroll
    for (int mf = 0; mf < 2; mf++)
#pragma unroll
        for (int nf = 0; nf < 4; nf++) {
            int row = m0 + wm + mf * 16 + qr;
            int col = n0 + wn + nf * 8 + qc * 2;
            unsigned short p0 = fp8pack(c[mf][nf][0], c[mf][nf][1]);
            unsigned short p1 = fp8pack(c[mf][nf][2], c[mf][nf][3]);
            *(unsigned short*)(d_Kc8 + (size_t)row * 512 + col) = p0;
            *(unsigned short*)(d_Kc8 + (size_t)(row + 8) * 512 + col) = p1;
        }
}

// ---------------- per-iteration kernels ----------------
__global__ void gru_kernel(const float* __restrict__ Wih1, const float* __restrict__ Whh1,
                           const float* __restrict__ bih1, const float* __restrict__ bhh1,
                           const float* __restrict__ Wih2, const float* __restrict__ Whh2,
                           const float* __restrict__ bih2, const float* __restrict__ bhh2) {
    int b = blockIdx.x, r = blockIdx.y, t = threadIdx.x;   // 384 threads
    const float* Wih = r ? Wih2 : Wih1;
    const float* Whh = r ? Whh2 : Whh1;
    const float* bih = r ? bih2 : bih1;
    const float* bhh = r ? bhh2 : bhh1;
    float* q = r ? d_q2 : d_q1;
    const float* iq = r ? d_iq2 : d_iq1;

    __shared__ __align__(16) float sx[E], sh[E];
    __shared__ float gi[3 * E], gh[3 * E];
    if (t < E) { sx[t] = iq[b * E + t]; sh[t] = q[b * E + t]; }
    __syncthreads();

    float a = bih[t], cgh = bhh[t];
    const float4* wi = (const float4*)(Wih + t * E);
    const float4* wh = (const float4*)(Whh + t * E);
    const float4* x4 = (const float4*)sx;
    const float4* h4 = (const float4*)sh;
#pragma unroll 8
    for (int e4 = 0; e4 < E / 4; e4++) {
        float4 wa = wi[e4], wb = wh[e4], xv = x4[e4], hv = h4[e4];
        a = fmaf(wa.x, xv.x, a); a = fmaf(wa.y, xv.y, a);
        a = fmaf(wa.z, xv.z, a); a = fmaf(wa.w, xv.w, a);
        cgh = fmaf(wb.x, hv.x, cgh); cgh = fmaf(wb.y, hv.y, cgh);
        cgh = fmaf(wb.z, hv.z, cgh); cgh = fmaf(wb.w, hv.w, cgh);
    }
    gi[t] = a; gh[t] = cgh;
    __syncthreads();
    if (t < E) {
        float rr = sigmoidf_(gi[t] + gh[t]);
        float z  = sigmoidf_(gi[E + t] + gh[E + t]);
        float n  = tanhf(gi[2 * E + t] + rr * gh[2 * E + t]);
        q[b * E + t] = (1.0f - z) * n + z * sh[t];
    }
}

__global__ void qproj_kernel(const float* __restrict__ WQ1, const float* __restrict__ WQ2,
                             const float* __restrict__ WQ3, const float* __restrict__ WQ4) {
    int b = blockIdx.x, t = threadIdx.x;                    // 512 threads
    __shared__ __align__(16) float s1[E], s2[E];
    if (t < E) s1[t] = d_q1[b * E + t];
    else if (t < 2 * E) s2[t - E] = d_q2[b * E + t - E];
    if (t == 0) d_expsum[b] = 0.0f;    // reset for this iteration's score pass
    __syncthreads();
    int j = t >> 7, f = t & 127;
    const float* W = (j == 0) ? WQ1 : (j == 1) ? WQ2 : (j == 2) ? WQ3 : WQ4;
    const float4* w = (const float4*)(W + f * E);
    const float4* x = (const float4*)((j == 0 || j == 2) ? s1 : s2);
    float acc = 0.f;
#pragma unroll 8
    for (int e4 = 0; e4 < E / 4; e4++) {
        float4 a = w[e4], v = x[e4];
        acc = fmaf(a.x, v.x, acc); acc = fmaf(a.y, v.y, acc);
        acc = fmaf(a.z, v.z, acc); acc = fmaf(a.w, v.w, acc);
    }
    d_Qp[b * 512 + t] = acc;
}

__global__ void __launch_bounds__(256) score_kernel(int iter, const int* __restrict__ last_action,
                                                    const float* __restrict__ V1,
                                                    const float* __restrict__ V2) {
    int b = blockIdx.x, t = threadIdx.x;
    int warp = t >> 5, lane = t & 31;
    __shared__ float sQ[512];
    __shared__ float sV[256];
    __shared__ float sE[8];
    sQ[t] = d_Qp[b * 512 + t];
    sQ[256 + t] = d_Qp[b * 512 + 256 + t];
    sV[t] = (t < 128) ? V1[t] : V2[t - 128];
    __syncthreads();

    int g = blockIdx.y * 8 + warp;
    const unsigned char* __restrict__ Kc = d_Kc8 + ((size_t)b * GS + g) * 512;
    int f0 = lane * 4;
    unsigned u1 = *(const unsigned*)(Kc + f0);
    unsigned u2 = *(const unsigned*)(Kc + 128 + f0);
    unsigned u3 = *(const unsigned*)(Kc + 256 + f0);
    unsigned u4 = *(const unsigned*)(Kc + 384 + f0);
    float k1[4], k2[4], k3[4], k4[4];
    fp8x4_to_f32(u1, k1); fp8x4_to_f32(u2, k2);
    fp8x4_to_f32(u3, k3); fp8x4_to_f32(u4, k4);
    float s = 0.f;
#pragma unroll
    for (int i = 0; i < 4; i++) {
        int f = f0 + i;
        float a1 = fmaf(k3[i], sQ[256 + f], k1[i] + sQ[f]);
        float a2 = fmaf(k4[i], sQ[384 + f], k2[i] + sQ[128 + f]);
        s = fmaf(sV[f], tanh_fast(a1), s);
        s = fmaf(sV[128 + f], tanh_fast(a2), s);
    }
#pragma unroll
    for (int o = 16; o; o >>= 1) s += __shfl_xor_sync(0xFFFFFFFFu, s, o);
    if (lane == 0) {
        float lgt = tanhf(s) * CLIPV;
        bool m = (iter == 0) ? (g == last_action[b]) : (d_mask[b * GS + g] != 0);
        d_logits[b * GS + g] = m ? NEGV : lgt;
        sE[warp] = m ? 0.0f : expf(lgt - CLIPV);   // shifted by clip bound
    }
    __syncthreads();
    if (t == 0) {
        float e = sE[0];
#pragma unroll
        for (int i = 1; i < 8; i++) e += sE[i];
        atomicAdd(&d_expsum[b], e);
    }
}

__global__ void __launch_bounds__(256) update_kernel(int iter, const int* __restrict__ rec,
                                                     const int* __restrict__ vt,
                                                     const float* __restrict__ h,
                                                     const int* __restrict__ fixed_action) {
    int b = blockIdx.x, t = threadIdx.x;   // 256 threads, one block per b
    __shared__ int s_action, s_stopold, s_stopnew, s_nolmod, s_allow, s_ai0;

    const int bG = b * GS;

    if (t == 0) {
        int stop_old = d_stopped[b];
        int nol_old  = d_nol[b];
        int ai0_old  = d_ai[b * 4];
        int action   = (iter > 0 && stop_old) ? ai0_old : fixed_action[b * KM + iter];

        // expsum == 0 exactly <=> ALL logits masked (each unmasked entry adds
        // >= exp(-2*CLIP) > 0; masked entries add exactly 0.0f). In that case the
        // reference's shifted log-softmax gives logp[action] = -log(GS).
        float es = d_expsum[b];
        float loss = (es > 0.0f) ? (d_logits[bG + action] - (CLIPV + logf(es)))
                                 : (-logf((float)GS));
        if (iter == 0) d_ll[b] += loss;
        else if (!stop_old) d_ll[b] += loss;

        int nna = rec[bG + action];
        d_ai[b * 4 + iter] = action;
        if (stop_old) d_kl[b * 5 + iter] = action;
        int krm1 = ((iter - 1) + KM) % KM;
        if (!stop_old) d_kr[b * 4 + krm1] = action;
        d_kl[b * 5 + iter + 1] = nna;

        int eq = (action == nol_old) ? 1 : 0;
        int stop_new = (iter == 0) ? eq : (stop_old | eq);
        if (stop_new) {
            int klm1 = ((iter - 1) + 5) % 5;
            d_kl[b * 5 + iter] = d_kl[b * 5 + klm1];
            d_kr[b * 4 + iter] = d_kr[b * 4 + krm1];
        }
        d_stopped[b] = stop_new;
        d_nol[b] = stop_new ? -1 : nna;

        int ai0 = (iter == 0) ? action : ai0_old;
        s_action = action;
        s_stopold = stop_old;
        s_stopnew = stop_new;
        s_nolmod = ((nol_old % GS) + GS) % GS;   // Python floored mod
        s_ai0 = ai0;
        s_allow = (!stop_new && nna == ai0) ? 1 : 0;
    }
    __syncthreads();

    int act = s_action;
    int va = (iter == 0) ? 0 : d_vtt[bG + act];
    int vta = (iter == 0) ? vt[bG + act] : 0;
    for (int g = t; g < GS; g += 256) {
        int v;
        if (iter == 0) {
            v = (((vt[bG + g] - vta) % GS) + GS) % GS;
            d_vtt[bG + g] = v;
        } else {
            v = d_vtt[bG + g];
        }
        bool m = (v <= va);
        if (iter == 0) m = m || (v > GS - 2);
        if (s_stopnew && g == act) m = false;
        if (s_allow && g == s_ai0) m = false;
        d_mask[bG + g] = m ? 1 : 0;
    }

    if (t < E) {
        float hq1 = h[((size_t)bG + act) * E + t];
        d_iq1[b * E + t] = hq1;
        d_iq2[b * E + t] = s_stopold ? hq1 : h[((size_t)bG + s_nolmod) * E + t];
    }
}

// ---------------- output ----------------
__global__ void out_kernel(float* __restrict__ out) {
    int idx = blockIdx.x * 256 + threadIdx.x;
    if (idx < BS * 12) {
        int b = idx / 12, j = idx % 12;
        int v;
        if (j < 4) v = d_ai[b * 4 + j];
        else if (j < 8) v = d_kl[b * 5 + (j - 4)];
        else {
            int jj = j - 8;
            if (jj == 3 && !d_stopped[b]) v = d_kl[b * 5 + 4];  // post-loop kr fix
            else v = d_kr[b * 4 + jj];
        }
        out[idx] = (float)v;
    } else if (idx < BS * 12 + BS) {
        out[idx] = d_ll[idx - BS * 12];
    }
}

// ---------------- launch ----------------
extern "C" void kernel_launch(void* const* d_in, const int* in_sizes, int n_in,
                              void* d_out, int out_size) {
    (void)in_sizes; (void)n_in; (void)out_size;
    const float* h            = (const float*)d_in[0];
    const int*   rec          = (const int*)  d_in[1];
    /* context2 d_in[2] unused */
    const int*   visited_time = (const int*)  d_in[3];
    const int*   last_action  = (const int*)  d_in[4];
    const int*   fixed_action = (const int*)  d_in[5];
    const float* W_K1 = (const float*)d_in[6];
    const float* W_K2 = (const float*)d_in[7];
    const float* W_K3 = (const float*)d_in[8];
    const float* W_K4 = (const float*)d_in[9];
    const float* W_Q1 = (const float*)d_in[10];
    const float* W_Q2 = (const float*)d_in[11];
    const float* W_Q3 = (const float*)d_in[12];
    const float* W_Q4 = (const float*)d_in[13];
    const float* W_init     = (const float*)d_in[14];
    const float* b_init     = (const float*)d_in[15];
    const float* V1         = (const float*)d_in[16];
    const float* V2         = (const float*)d_in[17];
    const float* init_query = (const float*)d_in[18];
    const float* r1_Wih = (const float*)d_in[19];
    const float* r1_Whh = (const float*)d_in[20];
    const float* r1_bih = (const float*)d_in[21];
    const float* r1_bhh = (const float*)d_in[22];
    const float* r2_Wih = (const float*)d_in[23];
    const float* r2_Whh = (const float*)d_in[24];
    const float* r2_bih = (const float*)d_in[25];
    const float* r2_bhh = (const float*)d_in[26];

    convert_w<<<256, 256>>>(W_K1, W_K2, W_K3, W_K4);
    hmean_kernel<<<BS, 512>>>(h);
    init_kernel<<<BS, 128>>>(W_init, b_init, init_query);
    gemm_kernel<<<dim3(8, 4000), 128>>>(h);   // n fastest -> A tile L2 reuse

    for (int i = 0; i < KM; i++) {
        gru_kernel<<<dim3(BS, 2), 384>>>(r1_Wih, r1_Whh, r1_bih, r1_bhh,
                                         r2_Wih, r2_Whh, r2_bih, r2_bhh);
        qproj_kernel<<<BS, 512>>>(W_Q1, W_Q2, W_Q3, W_Q4);
        score_kernel<<<dim3(BS, 250), 256>>>(i, last_action, V1, V2);
        update_kernel<<<BS, 256>>>(i, rec, visited_time, h, fixed_action);
    }
    out_kernel<<<7, 256>>>((float*)d_out);
}

// round 10
// speedup vs baseline: 1.3311x; 1.0410x over previous
#include <cuda_runtime.h>
#include <cuda_bf16.h>
#include <cuda_fp16.h>
#include <math.h>
#include <stdint.h>

#define BS   128
#define GS   2000
#define E    128
#define KM   4
#define NEGV (-1.0e30f)
#define CLIPV 10.0f

// ---------------- device scratch (static globals; no runtime allocation) ----------------
__device__ unsigned char d_Kc8[(size_t)BS * GS * 512];  // [b][g][K1|K2|K3|K4] e4m3 (131 MB)
__device__ __nv_bfloat16 d_Wb[512 * 128];               // [n=j*128+f][k=e] bf16 (col-major B)
__device__ float d_logits[BS * GS];
__device__ float d_expsum[BS];
__device__ unsigned char d_mask[BS * GS];
__device__ int   d_vtt[BS * GS];
__device__ float d_q1[BS * E], d_q2[BS * E];
__device__ float d_iq1[BS * E], d_iq2[BS * E];
__device__ float d_Qp[BS * 512];                        // [Q1|Q2|Q3|Q4] per b
__device__ float d_hmean[BS * E];
__device__ int   d_ai[BS * 4];
__device__ int   d_kl[BS * 5];
__device__ int   d_kr[BS * 4];
__device__ int   d_nol[BS];
__device__ int   d_stopped[BS];
__device__ float d_ll[BS];

// ---------------- math helpers ----------------
__device__ __forceinline__ float fast_rcp(float x) {
    float r = __uint_as_float(0x7EF311C3u - __float_as_uint(x));
    r = r * (2.0f - x * r);
    r = r * (2.0f - x * r);
    return r;
}
__device__ __forceinline__ float tanh_fast(float x) {
    // Pade(5,4), clamp 3.6; abs err <= ~1e-3; fma/alu pipes only
    float xc = fminf(fmaxf(x, -3.6f), 3.6f);
    float x2 = xc * xc;
    float num = xc * fmaf(x2, x2 + 105.0f, 945.0f);
    float den = fmaf(x2, fmaf(15.0f, x2, 420.0f), 945.0f);
    return num * fast_rcp(den);
}
__device__ __forceinline__ float sigmoidf_(float x) { return 1.0f / (1.0f + expf(-x)); }

// pack two f32 -> e4m3x2 (byte0 = a, byte1 = b)
__device__ __forceinline__ unsigned short fp8pack(float a, float b) {
    unsigned short p;
    asm("cvt.rn.satfinite.e4m3x2.f32 %0, %1, %2;" : "=h"(p) : "f"(b), "f"(a));
    return p;
}
// 4 e4m3 bytes -> 4 floats (o[0] = byte0 ...)
__device__ __forceinline__ void fp8x4_to_f32(unsigned u, float* o) {
    unsigned h01, h23;
    asm("{\n\t.reg .b16 lo, hi;\n\t"
        "mov.b32 {lo, hi}, %2;\n\t"
        "cvt.rn.f16x2.e4m3x2 %0, lo;\n\t"
        "cvt.rn.f16x2.e4m3x2 %1, hi;\n\t}"
        : "=r"(h01), "=r"(h23) : "r"(u));
    float2 x = __half22float2(*reinterpret_cast<__half2*>(&h01));
    float2 y = __half22float2(*reinterpret_cast<__half2*>(&h23));
    o[0] = x.x; o[1] = x.y; o[2] = y.x; o[3] = y.y;
}

#define LDSM4(r, addr) \
    asm volatile("ldmatrix.sync.aligned.m8n8.x4.shared.b16 {%0,%1,%2,%3}, [%4];" \
                 : "=r"((r)[0]), "=r"((r)[1]), "=r"((r)[2]), "=r"((r)[3]) : "r"(addr))

#define MMA16816(c, a, b0, b1) \
    asm volatile("mma.sync.aligned.m16n8k16.row.col.f32.bf16.bf16.f32 " \
                 "{%0,%1,%2,%3},{%4,%5,%6,%7},{%8,%9},{%0,%1,%2,%3};" \
                 : "+f"((c)[0]), "+f"((c)[1]), "+f"((c)[2]), "+f"((c)[3]) \
                 : "r"((a)[0]), "r"((a)[1]), "r"((a)[2]), "r"((a)[3]), "r"(b0), "r"(b1))

// ---------------- setup kernels ----------------
__global__ void convert_w(const float* __restrict__ W1, const float* __restrict__ W2,
                          const float* __restrict__ W3, const float* __restrict__ W4) {
    int idx = blockIdx.x * blockDim.x + threadIdx.x;    // 65536
    if (idx >= 512 * 128) return;
    int j = idx >> 14, r = idx & 16383;
    const float* W = (j == 0) ? W1 : (j == 1) ? W2 : (j == 2) ? W3 : W4;
    d_Wb[idx] = __float2bfloat16(W[r]);
}

__global__ void hmean_kernel(const float* __restrict__ h) {
    int b = blockIdx.x, t = threadIdx.x;                 // 512 threads
    int e = t & 127, q = t >> 7;
    __shared__ float part[4][128];
    float s = 0.f;
    for (int g = q * 500; g < (q + 1) * 500; g++)
        s += h[((size_t)b * GS + g) * E + e];
    part[q][e] = s;
    __syncthreads();
    if (t < 128)
        d_hmean[b * E + t] = (part[0][t] + part[1][t] + part[2][t] + part[3][t]) * (1.0f / GS);
}

__global__ void init_kernel(const float* __restrict__ W_init, const float* __restrict__ b_init,
                            const float* __restrict__ init_query) {
    int b = blockIdx.x, t = threadIdx.x;                 // 128 threads
    __shared__ __align__(16) float sm[E];
    sm[t] = d_hmean[b * E + t];
    __syncthreads();
    float acc = b_init[t];
    const float4* w = (const float4*)(W_init + t * E);
    const float4* x = (const float4*)sm;
#pragma unroll 8
    for (int e4 = 0; e4 < E / 4; e4++) {
        float4 a = w[e4], v = x[e4];
        acc = fmaf(a.x, v.x, acc); acc = fmaf(a.y, v.y, acc);
        acc = fmaf(a.z, v.z, acc); acc = fmaf(a.w, v.w, acc);
    }
    d_q1[b * E + t] = acc;
    d_q2[b * E + t] = acc;
    float iq = init_query[t];
    d_iq1[b * E + t] = iq;
    d_iq2[b * E + t] = iq;
    if (t == 0) { d_stopped[b] = 1; d_nol[b] = -1; d_ll[b] = 0.0f; }
    if (t < 5) d_kl[b * 5 + t] = 0;
    if (t < 4) { d_ai[b * 4 + t] = 0; d_kr[b * 4 + t] = 0; }
}

// ---------------- bf16 MMA GEMM via ldmatrix: Kc8 = e4m3(h @ W^T) ----------------
// Tile 128m x 64n, 256 threads (8 warps = 4m x 2n), warp does 32x32.
// K split into two 64-halves staged through one A smem buffer.
// grid (8_n, 2000_m): n fastest -> A tile L2-resident across its 8 n-blocks.
__global__ void __launch_bounds__(256) gemm_kernel(const float* __restrict__ A) {
    __shared__ __nv_bfloat16 As[128][72];   // 144B rows: ldmatrix conflict-free (4-bank skew)
    __shared__ __nv_bfloat16 Bs[64][136];   // 272B rows: same property
    const int t = threadIdx.x;
    const int warp = t >> 5, lane = t & 31;
    const int n0 = blockIdx.x * 64, m0 = blockIdx.y * 128;
    const int wm = (warp >> 1) * 32, wn = (warp & 1) * 32;

    // load B once: 64 n-rows x 128 k bf16 (straight copy)
#pragma unroll
    for (int i = t; i < 64 * 16; i += 256) {
        int n = i >> 4, c8 = i & 15;
        *(uint4*)&Bs[n][c8 * 8] = *(const uint4*)(d_Wb + (size_t)(n0 + n) * 128 + c8 * 8);
    }

    float c[2][4][4];
#pragma unroll
    for (int i = 0; i < 2; i++)
#pragma unroll
        for (int j = 0; j < 4; j++)
#pragma unroll
            for (int k = 0; k < 4; k++) c[i][j][k] = 0.f;

    // ldmatrix lane address mapping
    // A (16x16 tile -> a0..a3): row = lane&15, col-half = (lane>>4)*8
    const int a_row = (lane & 15), a_colh = (lane >> 4) * 8;
    // B x4 (two 8n x 16k tiles): row = +8 if lane>=16, col-half = 8 if (lane>>3)&1
    const int b_row = ((lane >> 4) & 1) * 8 + (lane & 7);
    const int b_colh = ((lane >> 3) & 1) * 8;

    unsigned a_addr0 = (unsigned)__cvta_generic_to_shared(&As[wm + a_row][a_colh]);
    unsigned a_addr1 = (unsigned)__cvta_generic_to_shared(&As[wm + 16 + a_row][a_colh]);
    unsigned b_addr0 = (unsigned)__cvta_generic_to_shared(&Bs[wn + b_row][b_colh]);
    unsigned b_addr1 = (unsigned)__cvta_generic_to_shared(&Bs[wn + 16 + b_row][b_colh]);

#pragma unroll
    for (int kh = 0; kh < 2; kh++) {
        __syncthreads();   // protect As reuse (and B visibility on first pass)
        // load A half: 128 rows x 64 k fp32 -> bf16
#pragma unroll
        for (int i = t; i < 128 * 16; i += 256) {
            int row = i >> 4, c4 = i & 15;
            float4 v = *(const float4*)(A + (size_t)(m0 + row) * 128 + kh * 64 + c4 * 4);
            __nv_bfloat162 lo = __floats2bfloat162_rn(v.x, v.y);
            __nv_bfloat162 hi = __floats2bfloat162_rn(v.z, v.w);
            *(uint2*)&As[row][c4 * 4] = make_uint2(*(unsigned*)&lo, *(unsigned*)&hi);
        }
        __syncthreads();
#pragma unroll
        for (int ks = 0; ks < 4; ks++) {
            unsigned koff = ks * 32;                 // 16 bf16 cols
            unsigned bkoff = kh * 128 + ks * 32;
            unsigned af0[4], af1[4], bf0[4], bf1[4];
            LDSM4(af0, a_addr0 + koff);
            LDSM4(af1, a_addr1 + koff);
            LDSM4(bf0, b_addr0 + bkoff);
            LDSM4(bf1, b_addr1 + bkoff);
            MMA16816(c[0][0], af0, bf0[0], bf0[1]);
            MMA16816(c[0][1], af0, bf0[2], bf0[3]);
            MMA16816(c[0][2], af0, bf1[0], bf1[1]);
            MMA16816(c[0][3], af0, bf1[2], bf1[3]);
            MMA16816(c[1][0], af1, bf0[0], bf0[1]);
            MMA16816(c[1][1], af1, bf0[2], bf0[3]);
            MMA16816(c[1][2], af1, bf1[0], bf1[1]);
            MMA16816(c[1][3], af1, bf1[2], bf1[3]);
        }
    }

    // epilogue: e4m3 store (2 bytes per fragment row-pair)
    const int qr = lane >> 2, qc = lane & 3;
#pragma unroll
    for (int mf = 0; mf < 2; mf++)
#pragma unroll
        for (int nf = 0; nf < 4; nf++) {
            int row = m0 + wm + mf * 16 + qr;
            int col = n0 + wn + nf * 8 + qc * 2;
            unsigned short p0 = fp8pack(c[mf][nf][0], c[mf][nf][1]);
            unsigned short p1 = fp8pack(c[mf][nf][2], c[mf][nf][3]);
            *(unsigned short*)(d_Kc8 + (size_t)row * 512 + col) = p0;
            *(unsigned short*)(d_Kc8 + (size_t)(row + 8) * 512 + col) = p1;
        }
}

// ---------------- per-iteration kernels ----------------
__global__ void gru_kernel(const float* __restrict__ Wih1, const float* __restrict__ Whh1,
                           const float* __restrict__ bih1, const float* __restrict__ bhh1,
                           const float* __restrict__ Wih2, const float* __restrict__ Whh2,
                           const float* __restrict__ bih2, const float* __restrict__ bhh2) {
    int b = blockIdx.x, r = blockIdx.y, t = threadIdx.x;   // 384 threads
    const float* Wih = r ? Wih2 : Wih1;
    const float* Whh = r ? Whh2 : Whh1;
    const float* bih = r ? bih2 : bih1;
    const float* bhh = r ? bhh2 : bhh1;
    float* q = r ? d_q2 : d_q1;
    const float* iq = r ? d_iq2 : d_iq1;

    __shared__ __align__(16) float sx[E], sh[E];
    __shared__ float gi[3 * E], gh[3 * E];
    if (t < E) { sx[t] = iq[b * E + t]; sh[t] = q[b * E + t]; }
    __syncthreads();

    float a = bih[t], cgh = bhh[t];
    const float4* wi = (const float4*)(Wih + t * E);
    const float4* wh = (const float4*)(Whh + t * E);
    const float4* x4 = (const float4*)sx;
    const float4* h4 = (const float4*)sh;
#pragma unroll 8
    for (int e4 = 0; e4 < E / 4; e4++) {
        float4 wa = wi[e4], wb = wh[e4], xv = x4[e4], hv = h4[e4];
        a = fmaf(wa.x, xv.x, a); a = fmaf(wa.y, xv.y, a);
        a = fmaf(wa.z, xv.z, a); a = fmaf(wa.w, xv.w, a);
        cgh = fmaf(wb.x, hv.x, cgh); cgh = fmaf(wb.y, hv.y, cgh);
        cgh = fmaf(wb.z, hv.z, cgh); cgh = fmaf(wb.w, hv.w, cgh);
    }
    gi[t] = a; gh[t] = cgh;
    __syncthreads();
    if (t < E) {
        float rr = sigmoidf_(gi[t] + gh[t]);
        float z  = sigmoidf_(gi[E + t] + gh[E + t]);
        float n  = tanhf(gi[2 * E + t] + rr * gh[2 * E + t]);
        q[b * E + t] = (1.0f - z) * n + z * sh[t];
    }
}

__global__ void qproj_kernel(const float* __restrict__ WQ1, const float* __restrict__ WQ2,
                             const float* __restrict__ WQ3, const float* __restrict__ WQ4) {
    int b = blockIdx.x, t = threadIdx.x;                    // 512 threads
    __shared__ __align__(16) float s1[E], s2[E];
    if (t < E) s1[t] = d_q1[b * E + t];
    else if (t < 2 * E) s2[t - E] = d_q2[b * E + t - E];
    if (t == 0) d_expsum[b] = 0.0f;    // reset for this iteration's score pass
    __syncthreads();
    int j = t >> 7, f = t & 127;
    const float* W = (j == 0) ? WQ1 : (j == 1) ? WQ2 : (j == 2) ? WQ3 : WQ4;
    const float4* w = (const float4*)(W + f * E);
    const float4* x = (const float4*)((j == 0 || j == 2) ? s1 : s2);
    float acc = 0.f;
#pragma unroll 8
    for (int e4 = 0; e4 < E / 4; e4++) {
        float4 a = w[e4], v = x[e4];
        acc = fmaf(a.x, v.x, acc); acc = fmaf(a.y, v.y, acc);
        acc = fmaf(a.z, v.z, acc); acc = fmaf(a.w, v.w, acc);
    }
    d_Qp[b * 512 + t] = acc;
}

__global__ void __launch_bounds__(256) score_kernel(int iter, const int* __restrict__ last_action,
                                                    const float* __restrict__ V1,
                                                    const float* __restrict__ V2) {
    int b = blockIdx.x, t = threadIdx.x;
    int warp = t >> 5, lane = t & 31;
    __shared__ float sQ[512];
    __shared__ float sV[256];
    __shared__ float sE[8];
    sQ[t] = d_Qp[b * 512 + t];
    sQ[256 + t] = d_Qp[b * 512 + 256 + t];
    sV[t] = (t < 128) ? V1[t] : V2[t - 128];
    __syncthreads();

    int g = blockIdx.y * 8 + warp;
    const unsigned char* __restrict__ Kc = d_Kc8 + ((size_t)b * GS + g) * 512;
    int f0 = lane * 4;
    unsigned u1 = *(const unsigned*)(Kc + f0);
    unsigned u2 = *(const unsigned*)(Kc + 128 + f0);
    unsigned u3 = *(const unsigned*)(Kc + 256 + f0);
    unsigned u4 = *(const unsigned*)(Kc + 384 + f0);
    float k1[4], k2[4], k3[4], k4[4];
    fp8x4_to_f32(u1, k1); fp8x4_to_f32(u2, k2);
    fp8x4_to_f32(u3, k3); fp8x4_to_f32(u4, k4);
    float s = 0.f;
#pragma unroll
    for (int i = 0; i < 4; i++) {
        int f = f0 + i;
        float a1 = fmaf(k3[i], sQ[256 + f], k1[i] + sQ[f]);
        float a2 = fmaf(k4[i], sQ[384 + f], k2[i] + sQ[128 + f]);
        s = fmaf(sV[f], tanh_fast(a1), s);
        s = fmaf(sV[128 + f], tanh_fast(a2), s);
    }
#pragma unroll
    for (int o = 16; o; o >>= 1) s += __shfl_xor_sync(0xFFFFFFFFu, s, o);
    if (lane == 0) {
        float lgt = tanhf(s) * CLIPV;
        bool m = (iter == 0) ? (g == last_action[b]) : (d_mask[b * GS + g] != 0);
        d_logits[b * GS + g] = m ? NEGV : lgt;
        sE[warp] = m ? 0.0f : expf(lgt - CLIPV);   // shifted by clip bound
    }
    __syncthreads();
    if (t == 0) {
        float e = sE[0];
#pragma unroll
        for (int i = 1; i < 8; i++) e += sE[i];
        atomicAdd(&d_expsum[b], e);
    }
}

__global__ void __launch_bounds__(256) update_kernel(int iter, const int* __restrict__ rec,
                                                     const int* __restrict__ vt,
                                                     const float* __restrict__ h,
                                                     const int* __restrict__ fixed_action) {
    int b = blockIdx.x, t = threadIdx.x;   // 256 threads, one block per b
    __shared__ int s_action, s_stopold, s_stopnew, s_nolmod, s_allow, s_ai0;

    const int bG = b * GS;

    if (t == 0) {
        int stop_old = d_stopped[b];
        int nol_old  = d_nol[b];
        int ai0_old  = d_ai[b * 4];
        int action   = (iter > 0 && stop_old) ? ai0_old : fixed_action[b * KM + iter];

        // expsum == 0 exactly <=> ALL logits masked. Reference's shifted
        // log-softmax gives logp[action] = -log(GS) in that case.
        float es = d_expsum[b];
        float loss = (es > 0.0f) ? (d_logits[bG + action] - (CLIPV + logf(es)))
                                 : (-logf((float)GS));
        if (iter == 0) d_ll[b] += loss;
        else if (!stop_old) d_ll[b] += loss;

        int nna = rec[bG + action];
        d_ai[b * 4 + iter] = action;
        if (stop_old) d_kl[b * 5 + iter] = action;
        int krm1 = ((iter - 1) + KM) % KM;
        if (!stop_old) d_kr[b * 4 + krm1] = action;
        d_kl[b * 5 + iter + 1] = nna;

        int eq = (action == nol_old) ? 1 : 0;
        int stop_new = (iter == 0) ? eq : (stop_old | eq);
        if (stop_new) {
            int klm1 = ((iter - 1) + 5) % 5;
            d_kl[b * 5 + iter] = d_kl[b * 5 + klm1];
            d_kr[b * 4 + iter] = d_kr[b * 4 + krm1];
        }
        d_stopped[b] = stop_new;
        d_nol[b] = stop_new ? -1 : nna;

        int ai0 = (iter == 0) ? action : ai0_old;
        s_action = action;
        s_stopold = stop_old;
        s_stopnew = stop_new;
        s_nolmod = ((nol_old % GS) + GS) % GS;   // Python floored mod
        s_ai0 = ai0;
        s_allow = (!stop_new && nna == ai0) ? 1 : 0;
    }
    __syncthreads();

    int act = s_action;
    int va = (iter == 0) ? 0 : d_vtt[bG + act];
    int vta = (iter == 0) ? vt[bG + act] : 0;
    for (int g = t; g < GS; g += 256) {
        int v;
        if (iter == 0) {
            v = (((vt[bG + g] - vta) % GS) + GS) % GS;
            d_vtt[bG + g] = v;
        } else {
            v = d_vtt[bG + g];
        }
        bool m = (v <= va);
        if (iter == 0) m = m || (v > GS - 2);
        if (s_stopnew && g == act) m = false;
        if (s_allow && g == s_ai0) m = false;
        d_mask[bG + g] = m ? 1 : 0;
    }

    if (t < E) {
        float hq1 = h[((size_t)bG + act) * E + t];
        d_iq1[b * E + t] = hq1;
        d_iq2[b * E + t] = s_stopold ? hq1 : h[((size_t)bG + s_nolmod) * E + t];
    }
}

// ---------------- output ----------------
__global__ void out_kernel(float* __restrict__ out) {
    int idx = blockIdx.x * 256 + threadIdx.x;
    if (idx < BS * 12) {
        int b = idx / 12, j = idx % 12;
        int v;
        if (j < 4) v = d_ai[b * 4 + j];
        else if (j < 8) v = d_kl[b * 5 + (j - 4)];
        else {
            int jj = j - 8;
            if (jj == 3 && !d_stopped[b]) v = d_kl[b * 5 + 4];  // post-loop kr fix
            else v = d_kr[b * 4 + jj];
        }
        out[idx] = (float)v;
    } else if (idx < BS * 12 + BS) {
        out[idx] = d_ll[idx - BS * 12];
    }
}

// ---------------- launch ----------------
extern "C" void kernel_launch(void* const* d_in, const int* in_sizes, int n_in,
                              void* d_out, int out_size) {
    (void)in_sizes; (void)n_in; (void)out_size;
    const float* h            = (const float*)d_in[0];
    const int*   rec          = (const int*)  d_in[1];
    /* context2 d_in[2] unused */
    const int*   visited_time = (const int*)  d_in[3];
    const int*   last_action  = (const int*)  d_in[4];
    const int*   fixed_action = (const int*)  d_in[5];
    const float* W_K1 = (const float*)d_in[6];
    const float* W_K2 = (const float*)d_in[7];
    const float* W_K3 = (const float*)d_in[8];
    const float* W_K4 = (const float*)d_in[9];
    const float* W_Q1 = (const float*)d_in[10];
    const float* W_Q2 = (const float*)d_in[11];
    const float* W_Q3 = (const float*)d_in[12];
    const float* W_Q4 = (const float*)d_in[13];
    const float* W_init     = (const float*)d_in[14];
    const float* b_init     = (const float*)d_in[15];
    const float* V1         = (const float*)d_in[16];
    const float* V2         = (const float*)d_in[17];
    const float* init_query = (const float*)d_in[18];
    const float* r1_Wih = (const float*)d_in[19];
    const float* r1_Whh = (const float*)d_in[20];
    const float* r1_bih = (const float*)d_in[21];
    const float* r1_bhh = (const float*)d_in[22];
    const float* r2_Wih = (const float*)d_in[23];
    const float* r2_Whh = (const float*)d_in[24];
    const float* r2_bih = (const float*)d_in[25];
    const float* r2_bhh = (const float*)d_in[26];

    convert_w<<<256, 256>>>(W_K1, W_K2, W_K3, W_K4);
    hmean_kernel<<<BS, 512>>>(h);
    init_kernel<<<BS, 128>>>(W_init, b_init, init_query);
    gemm_kernel<<<dim3(8, 2000), 256>>>(h);   // n fastest -> A tile L2 reuse

    for (int i = 0; i < KM; i++) {
        gru_kernel<<<dim3(BS, 2), 384>>>(r1_Wih, r1_Whh, r1_bih, r1_bhh,
                                         r2_Wih, r2_Whh, r2_bih, r2_bhh);
        qproj_kernel<<<BS, 512>>>(W_Q1, W_Q2, W_Q3, W_Q4);
        score_kernel<<<dim3(BS, 250), 256>>>(i, last_action, V1, V2);
        update_kernel<<<BS, 256>>>(i, rec, visited_time, h, fixed_action);
    }
    out_kernel<<<7, 256>>>((float*)d_out);
}